// round 1
// baseline (speedup 1.0000x reference)
#include <cuda_runtime.h>

#define BB 2
#define CC 64
#define HH 48
#define WWn 48
#define LL 48
#define HWn (HH*WWn)            // 2304
#define SS (HH*WWn*LL)          // 110592
#define GHn 24
#define GSS (GHn*GHn*GHn)       // 13824
#define NCHUNK 108
#define CHUNKSZ 1024            // NCHUNK*CHUNKSZ == SS
#define NSITES (BB*HWn)         // 4608
#define TOTAL (BB*CC*SS)        // 14155776

// ---------------- scratch (device globals; no allocations) ----------------
__device__ float g_tx[TOTAL];          // theta_x, full res
__device__ float g_tg[TOTAL];          // theta_g, upsampled full res
__device__ float g_tgl[BB*CC*GSS];     // theta_g, low res
__device__ unsigned g_min_p_key;
__device__ unsigned g_min_d_key;
__device__ float g_part_p[BB*CC*NCHUNK];
__device__ float g_s1[BB*CC];
__device__ float g_sitesum[NSITES];
__device__ float g_s2[BB];

// order-preserving float<->uint key (atomicMin exact & deterministic)
__device__ __forceinline__ unsigned fkey(float f) {
    unsigned u = __float_as_uint(f);
    return (u & 0x80000000u) ? ~u : (u | 0x80000000u);
}
__device__ __forceinline__ float funkey(unsigned k) {
    unsigned u = (k & 0x80000000u) ? (k ^ 0x80000000u) : ~k;
    return __uint_as_float(u);
}

__global__ void k_init() {
    g_min_p_key = 0xFFFFFFFFu;
    g_min_d_key = 0xFFFFFFFFu;
}

// ---------------- 1x1x1 conv == channel-mix matvec per spatial site --------
__global__ void k_chanmix(const float* __restrict__ in,
                          const float* __restrict__ Wm,
                          const float* __restrict__ bias,
                          int which, int Ssz) {
    __shared__ float Ws[CC*CC];
    __shared__ float bs[CC];
    for (int i = threadIdx.x; i < CC*CC; i += blockDim.x) Ws[i] = Wm[i];
    if (threadIdx.x < CC) bs[threadIdx.x] = bias[threadIdx.x];
    __syncthreads();

    int e = blockIdx.x * blockDim.x + threadIdx.x;
    if (e >= BB * Ssz) return;
    int b  = e / Ssz;
    int sp = e - b * Ssz;

    const float* xb = in + (size_t)b * CC * Ssz + sp;
    float xr[CC];
#pragma unroll
    for (int c = 0; c < CC; c++) xr[c] = xb[(size_t)c * Ssz];

    float* out = which ? (float*)g_tgl : (float*)g_tx;
    size_t obase = (size_t)b * CC * Ssz + sp;
#pragma unroll 2
    for (int o = 0; o < CC; o++) {
        float acc = bs[o];
#pragma unroll
        for (int c = 0; c < CC; c++) acc = fmaf(Ws[o*CC + c], xr[c], acc);
        out[obase + (size_t)o * Ssz] = acc;
    }
}

// ---------------- trilinear x2 upsample (half-pixel, clamp == jax renorm) --
__device__ __forceinline__ void lintap(int o, int& i0, int& i1, float& w1) {
    float coord = 0.5f * (float)o - 0.25f;
    float ff = floorf(coord);
    w1 = coord - ff;
    int f = (int)ff;
    i0 = f < 0 ? 0 : f;
    i1 = (f + 1 > GHn - 1) ? (GHn - 1) : (f + 1);
}

__global__ void k_upsample() {
    int idx = blockIdx.x * blockDim.x + threadIdx.x;
    if (idx >= TOTAL) return;
    int l = idx % LL;  int t = idx / LL;
    int w = t % WWn;   t /= WWn;
    int h = t % HH;    int bc = t / HH;

    int h0,h1,w0,w1,l0,l1; float fh,fw,fl;
    lintap(h,h0,h1,fh); lintap(w,w0,w1,fw); lintap(l,l0,l1,fl);

    const float* base = g_tgl + (size_t)bc * GSS;
    float v000 = base[(h0*GHn + w0)*GHn + l0];
    float v001 = base[(h0*GHn + w0)*GHn + l1];
    float v010 = base[(h0*GHn + w1)*GHn + l0];
    float v011 = base[(h0*GHn + w1)*GHn + l1];
    float v100 = base[(h1*GHn + w0)*GHn + l0];
    float v101 = base[(h1*GHn + w0)*GHn + l1];
    float v110 = base[(h1*GHn + w1)*GHn + l0];
    float v111 = base[(h1*GHn + w1)*GHn + l1];

    float c00 = v000 + fl*(v001 - v000);
    float c01 = v010 + fl*(v011 - v010);
    float c10 = v100 + fl*(v101 - v100);
    float c11 = v110 + fl*(v111 - v110);
    float c0  = c00 + fw*(c01 - c00);
    float c1  = c10 + fw*(c11 - c10);
    g_tg[idx] = c0 + fh*(c1 - c0);
}

// ---------------- stats for p: global min + per-(b,c) sums ----------------
__global__ void k_stats_p() {
    int chunk = blockIdx.x;       // 0..NCHUNK-1
    int bc    = blockIdx.y;       // 0..B*C-1
    size_t base = (size_t)bc * SS + (size_t)chunk * CHUNKSZ;

    float lmin = 3.402823466e38f, lsum = 0.f;
    for (int i = threadIdx.x; i < CHUNKSZ; i += blockDim.x) {
        float t = g_tx[base + i] * g_tg[base + i];
        lmin = fminf(lmin, t);
        lsum += t;
    }
    __shared__ float smin[256], ssum[256];
    int tid = threadIdx.x;
    smin[tid] = lmin; ssum[tid] = lsum;
    __syncthreads();
    for (int st = 128; st > 0; st >>= 1) {
        if (tid < st) {
            smin[tid] = fminf(smin[tid], smin[tid + st]);
            ssum[tid] += ssum[tid + st];
        }
        __syncthreads();
    }
    if (tid == 0) {
        atomicMin(&g_min_p_key, fkey(smin[0]));
        g_part_p[bc * NCHUNK + chunk] = ssum[0];
    }
}

__global__ void k_reduce_p() {     // 128 blocks x 128 threads
    __shared__ float sh[128];
    int tid = threadIdx.x;
    float v = (tid < NCHUNK) ? g_part_p[blockIdx.x * NCHUNK + tid] : 0.f;
    sh[tid] = v;
    __syncthreads();
    for (int st = 64; st > 0; st >>= 1) {
        if (tid < st) sh[tid] += sh[tid + st];
        __syncthreads();
    }
    if (tid == 0) g_s1[blockIdx.x] = sh[0];
}

// ---------------- stats for d: raw = A*G^T per site (min + sum) -----------
__global__ void k_stats_d() {
    __shared__ float As[CC*49];
    __shared__ float Gs[CC*49];
    int site = blockIdx.x;
    int b = site / HWn, hw = site - b * HWn;
    size_t base = (size_t)b * CC * SS + (size_t)hw * LL;
    int tid = threadIdx.x;

    for (int i = tid; i < CC*LL; i += blockDim.x) {
        int c = i / LL, l = i - c * LL;
        As[c*49 + l] = g_tx[base + (size_t)c * SS + l];
        Gs[c*49 + l] = g_tg[base + (size_t)c * SS + l];
    }
    __syncthreads();

    int ti = tid >> 4, tj = tid & 15;
    float acc[4][4];
#pragma unroll
    for (int ii = 0; ii < 4; ii++)
#pragma unroll
        for (int jj = 0; jj < 4; jj++) acc[ii][jj] = 0.f;

    for (int l = 0; l < LL; l++) {
        float a[4], g[4];
#pragma unroll
        for (int k = 0; k < 4; k++) {
            a[k] = As[(ti + 16*k)*49 + l];
            g[k] = Gs[(tj + 16*k)*49 + l];
        }
#pragma unroll
        for (int ii = 0; ii < 4; ii++)
#pragma unroll
            for (int jj = 0; jj < 4; jj++)
                acc[ii][jj] = fmaf(a[ii], g[jj], acc[ii][jj]);
    }

    float lmin = 3.402823466e38f, lsum = 0.f;
#pragma unroll
    for (int ii = 0; ii < 4; ii++)
#pragma unroll
        for (int jj = 0; jj < 4; jj++) {
            lmin = fminf(lmin, acc[ii][jj]);
            lsum += acc[ii][jj];
        }

    __syncthreads();                 // reuse As as reduction buffers
    float* rmin = As;
    float* rsum = As + 256;
    rmin[tid] = lmin; rsum[tid] = lsum;
    __syncthreads();
    for (int st = 128; st > 0; st >>= 1) {
        if (tid < st) {
            rmin[tid] = fminf(rmin[tid], rmin[tid + st]);
            rsum[tid] += rsum[tid + st];
        }
        __syncthreads();
    }
    if (tid == 0) {
        atomicMin(&g_min_d_key, fkey(rmin[0]));
        g_sitesum[site] = rsum[0];
    }
}

__global__ void k_reduce_d() {    // BB blocks x 256 threads
    int b = blockIdx.x, tid = threadIdx.x;
    float s = 0.f;
    for (int i = tid; i < HWn; i += 256) s += g_sitesum[b * HWn + i];
    __shared__ float sh[256];
    sh[tid] = s;
    __syncthreads();
    for (int st = 128; st > 0; st >>= 1) {
        if (tid < st) sh[tid] += sh[tid + st];
        __syncthreads();
    }
    if (tid == 0) g_s2[b] = sh[0];
}

// ---------------- finalize p -----------------------------------------------
__global__ void k_p(const float* __restrict__ x, float* __restrict__ outp) {
    int idx = blockIdx.x * blockDim.x + threadIdx.x;
    if (idx >= TOTAL) return;
    int bc = idx / SS;
    float m1 = funkey(g_min_p_key);
    float denom = g_s1[bc] - m1 * (float)SS;
    float t = g_tx[idx] * g_tg[idx] - m1;
    outp[idx] = t * x[idx] / denom;
}

// ---------------- d: per-site D = (G*(A^T X) - m*colsum(X)) / S_b ----------
__global__ void k_d(const float* __restrict__ x, float* __restrict__ outd) {
    __shared__ float As[CC*49];
    __shared__ float Gs[CC*49];
    __shared__ float Xs[CC*49];
    __shared__ float Ms[LL*49];
    __shared__ float cs[LL];

    int site = blockIdx.x;
    int b = site / HWn, hw = site - b * HWn;
    size_t base = (size_t)b * CC * SS + (size_t)hw * LL;
    int tid = threadIdx.x;

    for (int i = tid; i < CC*LL; i += 256) {
        int c = i / LL, l = i - c * LL;
        As[c*49 + l] = g_tx[base + (size_t)c * SS + l];
        Gs[c*49 + l] = g_tg[base + (size_t)c * SS + l];
        Xs[c*49 + l] = x   [base + (size_t)c * SS + l];
    }
    __syncthreads();

    if (tid < LL) {
        float s = 0.f;
#pragma unroll
        for (int c = 0; c < CC; c++) s += Xs[c*49 + tid];
        cs[tid] = s;
    }

    int ti = tid >> 4, tj = tid & 15;

    // Phase 1: M[lp][l] = sum_c A[c][lp] * X[c][l]  (48x48), 3x3 per thread
    {
        float acc[3][3];
#pragma unroll
        for (int k = 0; k < 3; k++)
#pragma unroll
            for (int kk = 0; kk < 3; kk++) acc[k][kk] = 0.f;

        for (int c = 0; c < CC; c++) {
            float a[3], xx[3];
#pragma unroll
            for (int k = 0; k < 3; k++) {
                a[k]  = As[c*49 + ti + 16*k];
                xx[k] = Xs[c*49 + tj + 16*k];
            }
#pragma unroll
            for (int k = 0; k < 3; k++)
#pragma unroll
                for (int kk = 0; kk < 3; kk++)
                    acc[k][kk] = fmaf(a[k], xx[kk], acc[k][kk]);
        }
#pragma unroll
        for (int k = 0; k < 3; k++)
#pragma unroll
            for (int kk = 0; kk < 3; kk++)
                Ms[(ti + 16*k)*49 + (tj + 16*kk)] = acc[k][kk];
    }
    __syncthreads();

    // Phase 2: D[j][l] = sum_lp G[j][lp]*M[lp][l], 4(j)x3(l) per thread
    float m2 = funkey(g_min_d_key);
    float inv = 1.f / (g_s2[b] - m2 * 9437184.0f);   // HW*C*C per batch
    {
        float acc[4][3];
#pragma unroll
        for (int k = 0; k < 4; k++)
#pragma unroll
            for (int kk = 0; kk < 3; kk++) acc[k][kk] = 0.f;

        for (int lp = 0; lp < LL; lp++) {
            float gg[4], mm[3];
#pragma unroll
            for (int k = 0; k < 4; k++) gg[k] = Gs[(ti + 16*k)*49 + lp];
#pragma unroll
            for (int kk = 0; kk < 3; kk++) mm[kk] = Ms[lp*49 + tj + 16*kk];
#pragma unroll
            for (int k = 0; k < 4; k++)
#pragma unroll
                for (int kk = 0; kk < 3; kk++)
                    acc[k][kk] = fmaf(gg[k], mm[kk], acc[k][kk]);
        }
#pragma unroll
        for (int k = 0; k < 4; k++) {
            int j = ti + 16*k;
#pragma unroll
            for (int kk = 0; kk < 3; kk++) {
                int l = tj + 16*kk;
                outd[base + (size_t)j * SS + l] = (acc[k][kk] - m2 * cs[l]) * inv;
            }
        }
    }
}

// ---------------- launch ----------------------------------------------------
extern "C" void kernel_launch(void* const* d_in, const int* in_sizes, int n_in,
                              void* d_out, int out_size) {
    const float* x  = (const float*)d_in[0];
    const float* g  = (const float*)d_in[1];
    const float* W1 = (const float*)d_in[2];
    const float* b1 = (const float*)d_in[3];
    const float* W2 = (const float*)d_in[4];
    const float* b2 = (const float*)d_in[5];

    float* out  = (float*)d_out;
    float* outp = out;
    float* outd = out + (size_t)TOTAL;

    k_init<<<1, 1>>>();
    k_chanmix<<<(BB*SS  + 255)/256, 256>>>(x, W1, b1, 0, SS);
    k_chanmix<<<(BB*GSS + 255)/256, 256>>>(g, W2, b2, 1, GSS);
    k_upsample<<<(TOTAL + 255)/256, 256>>>();

    dim3 gp(NCHUNK, BB*CC);
    k_stats_p<<<gp, 256>>>();
    k_reduce_p<<<BB*CC, 128>>>();

    k_stats_d<<<NSITES, 256>>>();
    k_reduce_d<<<BB, 256>>>();

    k_p<<<(TOTAL + 255)/256, 256>>>(x, outp);
    k_d<<<NSITES, 256>>>(x, outd);
}

// round 2
// speedup vs baseline: 1.1440x; 1.1440x over previous
#include <cuda_runtime.h>

#define BB 2
#define CC 64
#define HH 48
#define WWn 48
#define LL 48
#define HWn (HH*WWn)            // 2304
#define SS (HH*WWn*LL)          // 110592
#define GHn 24
#define GSS (GHn*GHn*GHn)       // 13824
#define NCHUNK 108
#define NSITES (BB*HWn)         // 4608
#define TOTAL (BB*CC*SS)        // 14155776

// ---------------- scratch ----------------
__device__ float g_tx[TOTAL];
__device__ float g_tg[TOTAL];
__device__ float g_tgl[BB*CC*GSS];
__device__ unsigned g_min_p_key;
__device__ unsigned g_min_d_key;
__device__ float g_part_p[BB*CC*NCHUNK];
__device__ float g_s1[BB*CC];
__device__ float g_sitesum[NSITES];
__device__ float g_s2[BB];

__device__ __forceinline__ unsigned fkey(float f) {
    unsigned u = __float_as_uint(f);
    return (u & 0x80000000u) ? ~u : (u | 0x80000000u);
}
__device__ __forceinline__ float funkey(unsigned k) {
    unsigned u = (k & 0x80000000u) ? (k ^ 0x80000000u) : ~k;
    return __uint_as_float(u);
}

__global__ void k_init() {
    g_min_p_key = 0xFFFFFFFFu;
    g_min_d_key = 0xFFFFFFFFu;
}

// ---------------- channel-mix GEMM: 128 sites x 64 outs per block ----------
// smem: Wt[64][68] (transposed W), bs[64], Xs[64][132]
#define CM_SMEM ((64*68 + 64 + 64*132)*4)
__global__ __launch_bounds__(128, 4) void k_chanmix(
        const float* __restrict__ in, const float* __restrict__ Wm,
        const float* __restrict__ bias, int which, int Ssz) {
    extern __shared__ float dyn[];
    float* Wt  = dyn;             // 64*68
    float* bsm = Wt + 64*68;      // 64
    float* Xs  = bsm + 64;        // 64*132
    int tid = threadIdx.x;

    for (int i = tid; i < 4096; i += 128) {
        int o = i >> 6, c = i & 63;
        Wt[c*68 + o] = Wm[i];
    }
    if (tid < 64) bsm[tid] = bias[tid];

    int b = blockIdx.y;
    size_t sbase = (size_t)b * CC * Ssz + (size_t)blockIdx.x * 128;
    const float* src = in + sbase;
    for (int i = tid; i < 64*32; i += 128) {
        int c = i >> 5, sv = i & 31;
        float4 v = *(const float4*)(src + (size_t)c*Ssz + sv*4);
        *(float4*)&Xs[c*132 + sv*4] = v;
    }
    __syncthreads();

    int og = tid & 3;       // outputs og*16 .. og*16+15
    int sg = tid >> 2;      // sites   sg*4  .. sg*4+3
    float acc[16][4];
#pragma unroll
    for (int j = 0; j < 16; j++) {
        float bv = bsm[og*16 + j];
        acc[j][0]=bv; acc[j][1]=bv; acc[j][2]=bv; acc[j][3]=bv;
    }

#pragma unroll 4
    for (int c = 0; c < 64; c++) {
        float4 xv = *(const float4*)&Xs[c*132 + sg*4];
        float xk[4] = {xv.x, xv.y, xv.z, xv.w};
#pragma unroll
        for (int q = 0; q < 4; q++) {
            float4 wv = *(const float4*)&Wt[c*68 + og*16 + q*4];
            float wk[4] = {wv.x, wv.y, wv.z, wv.w};
#pragma unroll
            for (int jj = 0; jj < 4; jj++)
#pragma unroll
                for (int kk = 0; kk < 4; kk++)
                    acc[q*4+jj][kk] = fmaf(wk[jj], xk[kk], acc[q*4+jj][kk]);
        }
    }

    float* outp = (which ? (float*)g_tgl : (float*)g_tx) + sbase;
#pragma unroll
    for (int j = 0; j < 16; j++) {
        int o = og*16 + j;
        float4 v = make_float4(acc[j][0], acc[j][1], acc[j][2], acc[j][3]);
        *(float4*)(outp + (size_t)o*Ssz + sg*4) = v;
    }
}

// ---------------- trilinear x2 upsample: block per (bc, h) plane -----------
__global__ void k_upsample() {
    __shared__ float ph[24*25];
    int h  = blockIdx.x;
    int bc = blockIdx.y;

    int kh = h >> 1;
    int h0, h1; float fh;
    if ((h & 1) == 0) { h0 = kh-1 < 0 ? 0 : kh-1; h1 = kh;                      fh = 0.75f; }
    else              { h0 = kh;                  h1 = kh+1 > 23 ? 23 : kh+1;   fh = 0.25f; }

    const float* base = g_tgl + (size_t)bc * GSS;
    int tid = threadIdx.y * 48 + threadIdx.x;   // block (48,8)=384
    for (int i = tid; i < 576; i += 384) {
        float v0 = base[h0*576 + i];
        float v1 = base[h1*576 + i];
        int wi = i / 24, li = i - wi*24;
        ph[wi*25 + li] = v0 + fh*(v1 - v0);
    }
    __syncthreads();

    int l = threadIdx.x;
    int kl = l >> 1;
    int l0, l1; float fl;
    if ((l & 1) == 0) { l0 = kl-1 < 0 ? 0 : kl-1; l1 = kl;                    fl = 0.75f; }
    else              { l0 = kl;                  l1 = kl+1 > 23 ? 23 : kl+1; fl = 0.25f; }

    float* orow = g_tg + (size_t)bc * SS + (size_t)h * HWn;
    for (int w = threadIdx.y; w < 48; w += 8) {
        int kw = w >> 1;
        int w0, w1; float fw;
        if ((w & 1) == 0) { w0 = kw-1 < 0 ? 0 : kw-1; w1 = kw;                    fw = 0.75f; }
        else              { w0 = kw;                  w1 = kw+1 > 23 ? 23 : kw+1; fw = 0.25f; }
        float a0 = ph[w0*25 + l0], a1 = ph[w0*25 + l1];
        float b0 = ph[w1*25 + l0], b1 = ph[w1*25 + l1];
        float c0 = a0 + fl*(a1 - a0);
        float c1 = b0 + fl*(b1 - b0);
        orow[w*48 + l] = c0 + fw*(c1 - c0);
    }
}

// ---------------- stats for p ----------------------------------------------
__global__ void k_stats_p() {
    int bc = blockIdx.y;
    size_t base = (size_t)bc * SS + (size_t)blockIdx.x * 1024 + threadIdx.x * 4;
    float4 a = *(const float4*)(g_tx + base);
    float4 b = *(const float4*)(g_tg + base);
    float p0 = a.x*b.x, p1 = a.y*b.y, p2 = a.z*b.z, p3 = a.w*b.w;
    float lmin = fminf(fminf(p0,p1), fminf(p2,p3));
    float lsum = (p0+p1) + (p2+p3);
#pragma unroll
    for (int off = 16; off; off >>= 1) {
        lmin = fminf(lmin, __shfl_xor_sync(0xffffffffu, lmin, off));
        lsum += __shfl_xor_sync(0xffffffffu, lsum, off);
    }
    __shared__ float smin[8], ssum[8];
    int wid = threadIdx.x >> 5, lane = threadIdx.x & 31;
    if (!lane) { smin[wid] = lmin; ssum[wid] = lsum; }
    __syncthreads();
    if (threadIdx.x == 0) {
        float m = smin[0], s = ssum[0];
#pragma unroll
        for (int i = 1; i < 8; i++) { m = fminf(m, smin[i]); s += ssum[i]; }
        atomicMin(&g_min_p_key, fkey(m));
        g_part_p[bc * NCHUNK + blockIdx.x] = s;
    }
}

__global__ void k_reduce_p() {
    __shared__ float sh[128];
    int tid = threadIdx.x;
    float v = (tid < NCHUNK) ? g_part_p[blockIdx.x * NCHUNK + tid] : 0.f;
    sh[tid] = v;
    __syncthreads();
    for (int st = 64; st > 0; st >>= 1) {
        if (tid < st) sh[tid] += sh[tid + st];
        __syncthreads();
    }
    if (tid == 0) g_s1[blockIdx.x] = sh[0];
}

// ---------------- stats for d: raw = A*G^T, 2 sites/block, 8x8 tiles -------
#define SD_SMEM (2*2*3328*4)
__global__ __launch_bounds__(128, 4) void k_stats_d() {
    extern __shared__ float dyn[];
    float* Ab = dyn;            // [2][3328]
    float* Gb = dyn + 2*3328;   // [2][3328]
    __shared__ float rmin[4], rsum[4];
    int tid = threadIdx.x;

    for (int sj = 0; sj < 2; sj++) {
        int st = blockIdx.x*2 + sj;
        int b = st / HWn, hw = st - b*HWn;
        size_t gb = (size_t)b*CC*SS + (size_t)hw*LL;
        float* As = Ab + sj*3328;
        float* Gs = Gb + sj*3328;
        for (int i = tid; i < 64*12; i += 128) {
            int c = i / 12, lv = i - c*12;
            size_t off = gb + (size_t)c*SS + lv*4;
            *(float4*)&As[c*52 + lv*4] = *(const float4*)(g_tx + off);
            *(float4*)&Gs[c*52 + lv*4] = *(const float4*)(g_tg + off);
        }
    }
    __syncthreads();

    int sl = tid >> 6;
    int s  = tid & 63;
    int ti = s >> 3, tj = s & 7;
    const float* As = Ab + sl*3328;
    const float* Gs = Gb + sl*3328;

    float acc[8][8];
#pragma unroll
    for (int ii = 0; ii < 8; ii++)
#pragma unroll
        for (int jj = 0; jj < 8; jj++) acc[ii][jj] = 0.f;

    for (int l4 = 0; l4 < 12; l4++) {
#pragma unroll
        for (int half = 0; half < 2; half++) {
            float4 av[4];
#pragma unroll
            for (int k = 0; k < 4; k++)
                av[k] = *(const float4*)&As[(ti + 8*(half*4+k))*52 + l4*4];
#pragma unroll
            for (int jj = 0; jj < 8; jj++) {
                float4 gv = *(const float4*)&Gs[(tj + 8*jj)*52 + l4*4];
#pragma unroll
                for (int k = 0; k < 4; k++) {
                    int ii = half*4 + k;
                    acc[ii][jj] = fmaf(av[k].x, gv.x, acc[ii][jj]);
                    acc[ii][jj] = fmaf(av[k].y, gv.y, acc[ii][jj]);
                    acc[ii][jj] = fmaf(av[k].z, gv.z, acc[ii][jj]);
                    acc[ii][jj] = fmaf(av[k].w, gv.w, acc[ii][jj]);
                }
            }
        }
    }

    float lmin = acc[0][0], lsum = 0.f;
#pragma unroll
    for (int ii = 0; ii < 8; ii++)
#pragma unroll
        for (int jj = 0; jj < 8; jj++) {
            lmin = fminf(lmin, acc[ii][jj]);
            lsum += acc[ii][jj];
        }
#pragma unroll
    for (int off = 16; off; off >>= 1) {
        lmin = fminf(lmin, __shfl_xor_sync(0xffffffffu, lmin, off));
        lsum += __shfl_xor_sync(0xffffffffu, lsum, off);
    }
    int wid = tid >> 5, lane = tid & 31;
    if (!lane) { rmin[wid] = lmin; rsum[wid] = lsum; }
    __syncthreads();
    if (s == 0) {
        int w0 = sl*2;
        float m  = fminf(rmin[w0], rmin[w0+1]);
        float su = rsum[w0] + rsum[w0+1];
        atomicMin(&g_min_d_key, fkey(m));
        g_sitesum[blockIdx.x*2 + sl] = su;
    }
}

__global__ void k_reduce_d() {
    int b = blockIdx.x, tid = threadIdx.x;
    float s = 0.f;
    for (int i = tid; i < HWn; i += 256) s += g_sitesum[b * HWn + i];
    __shared__ float sh[256];
    sh[tid] = s;
    __syncthreads();
    for (int st = 128; st > 0; st >>= 1) {
        if (tid < st) sh[tid] += sh[tid + st];
        __syncthreads();
    }
    if (tid == 0) g_s2[b] = sh[0];
}

// ---------------- finalize p ------------------------------------------------
__global__ void k_p(const float* __restrict__ x, float* __restrict__ outp) {
    int bc = blockIdx.y;
    size_t base = (size_t)bc * SS + (size_t)blockIdx.x * 1024 + threadIdx.x * 4;
    float m1 = funkey(g_min_p_key);
    float inv = 1.0f / (g_s1[bc] - m1 * (float)SS);
    float4 a = *(const float4*)(g_tx + base);
    float4 b = *(const float4*)(g_tg + base);
    float4 xv = *(const float4*)(x + base);
    float4 o;
    o.x = (a.x*b.x - m1) * xv.x * inv;
    o.y = (a.y*b.y - m1) * xv.y * inv;
    o.z = (a.z*b.z - m1) * xv.z * inv;
    o.w = (a.w*b.w - m1) * xv.w * inv;
    *(float4*)(outp + base) = o;
}

// ---------------- d: per-site D = (G*(A^T X) - m*colsum(X)) / S_b ----------
#define KD_SMEM ((3328+3328+3264+2496+48)*4)
__global__ __launch_bounds__(128, 4) void k_d(const float* __restrict__ x,
                                              float* __restrict__ outd) {
    extern __shared__ float dyn[];
    float* As = dyn;            // 64*52
    float* Xs = As + 3328;      // 64*52
    float* Gt = Xs + 3328;      // 48*68 (transposed G: Gt[lp][j])
    float* Ms = Gt + 3264;      // 48*52
    float* cs = Ms + 2496;      // 48
    int tid = threadIdx.x;
    int site = blockIdx.x;
    int b = site / HWn, hw = site - b*HWn;
    size_t gb = (size_t)b*CC*SS + (size_t)hw*LL;

    for (int i = tid; i < 64*12; i += 128) {
        int c = i / 12, lv = i - c*12;
        size_t off = gb + (size_t)c*SS + lv*4;
        *(float4*)&As[c*52 + lv*4] = *(const float4*)(g_tx + off);
        *(float4*)&Xs[c*52 + lv*4] = *(const float4*)(x + off);
        float4 gg = *(const float4*)(g_tg + off);
        Gt[(lv*4+0)*68 + c] = gg.x;
        Gt[(lv*4+1)*68 + c] = gg.y;
        Gt[(lv*4+2)*68 + c] = gg.z;
        Gt[(lv*4+3)*68 + c] = gg.w;
    }
    __syncthreads();

    if (tid < 48) {
        float s = 0.f;
#pragma unroll 8
        for (int c = 0; c < 64; c++) s += Xs[c*52 + tid];
        cs[tid] = s;
    }

    // phase 1: M[lp][l] = sum_c A[c][lp] * X[c][l]
    {
        int ti = tid >> 3;   // 0..15 -> lp = ti*3 + ii
        int tj = tid & 7;    //        l  = tj*6 + jj
        float acc[3][6];
#pragma unroll
        for (int ii = 0; ii < 3; ii++)
#pragma unroll
            for (int jj = 0; jj < 6; jj++) acc[ii][jj] = 0.f;

#pragma unroll 4
        for (int c = 0; c < 64; c++) {
            float a0 = As[c*52 + ti*3 + 0];
            float a1 = As[c*52 + ti*3 + 1];
            float a2 = As[c*52 + ti*3 + 2];
            float xv[6];
#pragma unroll
            for (int jj = 0; jj < 6; jj++) xv[jj] = Xs[c*52 + tj*6 + jj];
#pragma unroll
            for (int jj = 0; jj < 6; jj++) {
                acc[0][jj] = fmaf(a0, xv[jj], acc[0][jj]);
                acc[1][jj] = fmaf(a1, xv[jj], acc[1][jj]);
                acc[2][jj] = fmaf(a2, xv[jj], acc[2][jj]);
            }
        }
#pragma unroll
        for (int ii = 0; ii < 3; ii++)
#pragma unroll
            for (int jj = 0; jj < 6; jj++)
                Ms[(ti*3+ii)*52 + tj*6 + jj] = acc[ii][jj];
    }
    __syncthreads();

    // phase 2: D[j][l] = sum_lp Gt[lp][j] * M[lp][l]
    float m2  = funkey(g_min_d_key);
    float inv = 1.0f / (g_s2[b] - m2 * 9437184.0f);   // HW*C*C per batch
    {
        int ti = tid >> 4;   // 0..7  -> j = ti*8 + k
        int tj = tid & 15;   //        l = tj*3 + m
        float acc[8][3];
#pragma unroll
        for (int k = 0; k < 8; k++)
#pragma unroll
            for (int m = 0; m < 3; m++) acc[k][m] = 0.f;

#pragma unroll 4
        for (int lp = 0; lp < 48; lp++) {
            float4 gA = *(const float4*)&Gt[lp*68 + ti*8];
            float4 gB = *(const float4*)&Gt[lp*68 + ti*8 + 4];
            float gk[8] = {gA.x,gA.y,gA.z,gA.w,gB.x,gB.y,gB.z,gB.w};
            float q0 = Ms[lp*52 + tj*3 + 0];
            float q1 = Ms[lp*52 + tj*3 + 1];
            float q2 = Ms[lp*52 + tj*3 + 2];
#pragma unroll
            for (int k = 0; k < 8; k++) {
                acc[k][0] = fmaf(gk[k], q0, acc[k][0]);
                acc[k][1] = fmaf(gk[k], q1, acc[k][1]);
                acc[k][2] = fmaf(gk[k], q2, acc[k][2]);
            }
        }

        float cc0 = cs[tj*3+0], cc1 = cs[tj*3+1], cc2 = cs[tj*3+2];
#pragma unroll
        for (int k = 0; k < 8; k++) {
            int j = ti*8 + k;
            size_t ob = gb + (size_t)j*SS + tj*3;
            outd[ob+0] = (acc[k][0] - m2*cc0) * inv;
            outd[ob+1] = (acc[k][1] - m2*cc1) * inv;
            outd[ob+2] = (acc[k][2] - m2*cc2) * inv;
        }
    }
}

// ---------------- launch ----------------------------------------------------
extern "C" void kernel_launch(void* const* d_in, const int* in_sizes, int n_in,
                              void* d_out, int out_size) {
    const float* x  = (const float*)d_in[0];
    const float* g  = (const float*)d_in[1];
    const float* W1 = (const float*)d_in[2];
    const float* b1 = (const float*)d_in[3];
    const float* W2 = (const float*)d_in[4];
    const float* b2 = (const float*)d_in[5];

    float* out  = (float*)d_out;
    float* outp = out;
    float* outd = out + (size_t)TOTAL;

    cudaFuncSetAttribute(k_chanmix, cudaFuncAttributeMaxDynamicSharedMemorySize, CM_SMEM);
    cudaFuncSetAttribute(k_stats_d, cudaFuncAttributeMaxDynamicSharedMemorySize, SD_SMEM);
    cudaFuncSetAttribute(k_d,       cudaFuncAttributeMaxDynamicSharedMemorySize, KD_SMEM);

    k_init<<<1, 1>>>();

    { dim3 gx(SS/128,  BB); k_chanmix<<<gx, 128, CM_SMEM>>>(x, W1, b1, 0, SS); }
    { dim3 gg(GSS/128, BB); k_chanmix<<<gg, 128, CM_SMEM>>>(g, W2, b2, 1, GSS); }
    { dim3 gu(HH, BB*CC);   k_upsample<<<gu, dim3(48, 8)>>>(); }

    { dim3 gp(NCHUNK, BB*CC); k_stats_p<<<gp, 256>>>(); }
    k_reduce_p<<<BB*CC, 128>>>();

    k_stats_d<<<NSITES/2, 128, SD_SMEM>>>();
    k_reduce_d<<<BB, 256>>>();

    { dim3 gq(NCHUNK, BB*CC); k_p<<<gq, 256>>>(x, outp); }
    k_d<<<NSITES, 128, KD_SMEM>>>(x, outd);
}

// round 3
// speedup vs baseline: 1.2467x; 1.0898x over previous
#include <cuda_runtime.h>

#define BB 2
#define CC 64
#define HH 48
#define WWn 48
#define LL 48
#define HWn (HH*WWn)            // 2304
#define SS (HH*WWn*LL)          // 110592
#define GHn 24
#define GSS (GHn*GHn*GHn)       // 13824
#define NSITES (BB*HWn)         // 4608
#define TOTAL (BB*CC*SS)        // 14155776

// ---------------- scratch ----------------
__device__ float g_tx[TOTAL];
__device__ float g_tg[TOTAL];
__device__ float g_tgl[BB*CC*GSS];
__device__ unsigned g_min_p_key;
__device__ unsigned g_min_d_key;
__device__ float g_sitechan[NSITES*CC];   // per-(site,channel) sums of tx*tg
__device__ float g_sitesum[NSITES];       // per-site sums of A*G^T
__device__ float g_inv1[BB*CC];
__device__ float g_inv2[BB];

__device__ __forceinline__ unsigned fkey(float f) {
    unsigned u = __float_as_uint(f);
    return (u & 0x80000000u) ? ~u : (u | 0x80000000u);
}
__device__ __forceinline__ float funkey(unsigned k) {
    unsigned u = (k & 0x80000000u) ? (k ^ 0x80000000u) : ~k;
    return __uint_as_float(u);
}

__global__ void k_init() {
    g_min_p_key = 0xFFFFFFFFu;
    g_min_d_key = 0xFFFFFFFFu;
}

// ---------------- channel-mix GEMM: 128 sites x 64 outs per block ----------
#define CM_SMEM ((64*68 + 64 + 64*132)*4)
__global__ __launch_bounds__(128, 4) void k_chanmix(
        const float* __restrict__ in, const float* __restrict__ Wm,
        const float* __restrict__ bias, int which, int Ssz) {
    extern __shared__ float dyn[];
    float* Wt  = dyn;             // 64*68
    float* bsm = Wt + 64*68;      // 64
    float* Xs  = bsm + 64;        // 64*132
    int tid = threadIdx.x;

    for (int i = tid; i < 4096; i += 128) {
        int o = i >> 6, c = i & 63;
        Wt[c*68 + o] = Wm[i];
    }
    if (tid < 64) bsm[tid] = bias[tid];

    int b = blockIdx.y;
    size_t sbase = (size_t)b * CC * Ssz + (size_t)blockIdx.x * 128;
    const float* src = in + sbase;
    for (int i = tid; i < 64*32; i += 128) {
        int c = i >> 5, sv = i & 31;
        float4 v = *(const float4*)(src + (size_t)c*Ssz + sv*4);
        *(float4*)&Xs[c*132 + sv*4] = v;
    }
    __syncthreads();

    int og = tid & 3;
    int sg = tid >> 2;
    float acc[16][4];
#pragma unroll
    for (int j = 0; j < 16; j++) {
        float bv = bsm[og*16 + j];
        acc[j][0]=bv; acc[j][1]=bv; acc[j][2]=bv; acc[j][3]=bv;
    }

#pragma unroll 4
    for (int c = 0; c < 64; c++) {
        float4 xv = *(const float4*)&Xs[c*132 + sg*4];
        float xk[4] = {xv.x, xv.y, xv.z, xv.w};
#pragma unroll
        for (int q = 0; q < 4; q++) {
            float4 wv = *(const float4*)&Wt[c*68 + og*16 + q*4];
            float wk[4] = {wv.x, wv.y, wv.z, wv.w};
#pragma unroll
            for (int jj = 0; jj < 4; jj++)
#pragma unroll
                for (int kk = 0; kk < 4; kk++)
                    acc[q*4+jj][kk] = fmaf(wk[jj], xk[kk], acc[q*4+jj][kk]);
        }
    }

    float* outp = (which ? (float*)g_tgl : (float*)g_tx) + sbase;
#pragma unroll
    for (int j = 0; j < 16; j++) {
        int o = og*16 + j;
        float4 v = make_float4(acc[j][0], acc[j][1], acc[j][2], acc[j][3]);
        *(float4*)(outp + (size_t)o*Ssz + sg*4) = v;
    }
}

// ---------------- trilinear x2 upsample -------------------------------------
// weights are always 0.75*near + 0.25*far (parity decides far direction)
__global__ void k_upsample() {
    __shared__ float ph[24*25];   // h-interp plane [w][l]
    int h  = blockIdx.x;
    int bc = blockIdx.y;

    int kh = h >> 1;
    int hf = (h & 1) ? (kh+1 > 23 ? 23 : kh+1) : (kh-1 < 0 ? 0 : kh-1);

    const float* bnear = g_tgl + (size_t)bc * GSS + kh*576;
    const float* bfar  = g_tgl + (size_t)bc * GSS + hf*576;
    int tid = threadIdx.y * 24 + threadIdx.x;   // block (24,16)=384
    for (int i = tid; i < 576; i += 384) {
        int wi = i / 24, li = i - wi*24;
        ph[wi*25 + li] = 0.75f*bnear[i] + 0.25f*bfar[i];
    }
    __syncthreads();

    int kl = threadIdx.x;                 // produces l = 2*kl, 2*kl+1
    int lm = kl-1 < 0 ? 0 : kl-1;
    int lp = kl+1 > 23 ? 23 : kl+1;

    float* orow = g_tg + (size_t)bc * SS + (size_t)h * HWn;
    for (int w = threadIdx.y; w < 48; w += 16) {
        int kw = w >> 1;
        int wf = (w & 1) ? (kw+1 > 23 ? 23 : kw+1) : (kw-1 < 0 ? 0 : kw-1);
        const float* rn = &ph[kw*25];
        const float* rf = &ph[wf*25];
        float um = 0.75f*rn[lm] + 0.25f*rf[lm];
        float uc = 0.75f*rn[kl] + 0.25f*rf[kl];
        float up = 0.75f*rn[lp] + 0.25f*rf[lp];
        float2 o;
        o.x = 0.25f*um + 0.75f*uc;
        o.y = 0.75f*uc + 0.25f*up;
        *(float2*)(orow + w*48 + 2*kl) = o;
    }
}

// ---- stats: raw = A*G^T per site (min+sum) AND elementwise tx*tg stats -----
#define SD_SMEM (2*2*3328*4)
__global__ __launch_bounds__(128, 4) void k_stats_d() {
    extern __shared__ float dyn[];
    float* Ab = dyn;            // [2][3328]
    float* Gb = dyn + 2*3328;
    __shared__ float rmin[4], rsum[4], pminw[4];
    int tid = threadIdx.x;

    for (int sj = 0; sj < 2; sj++) {
        int st = blockIdx.x*2 + sj;
        int b = st / HWn, hw = st - b*HWn;
        size_t gb = (size_t)b*CC*SS + (size_t)hw*LL;
        float* As = Ab + sj*3328;
        float* Gs = Gb + sj*3328;
        for (int i = tid; i < 64*12; i += 128) {
            int c = i / 12, lv = i - c*12;
            size_t off = gb + (size_t)c*SS + lv*4;
            *(float4*)&As[c*52 + lv*4] = *(const float4*)(g_tx + off);
            *(float4*)&Gs[c*52 + lv*4] = *(const float4*)(g_tg + off);
        }
    }
    __syncthreads();

    // ---- p stats: one channel-row per thread ----
    {
        int sl2 = tid >> 6, cch = tid & 63;
        const float* Ar = Ab + sl2*3328 + cch*52;
        const float* Gr = Gb + sl2*3328 + cch*52;
        float ps = 0.f, pm = 3.402823466e38f;
#pragma unroll
        for (int q = 0; q < 12; q++) {
            float4 a = *(const float4*)&Ar[q*4];
            float4 g = *(const float4*)&Gr[q*4];
            float t0 = a.x*g.x, t1 = a.y*g.y, t2 = a.z*g.z, t3 = a.w*g.w;
            ps += (t0+t1) + (t2+t3);
            pm = fminf(pm, fminf(fminf(t0,t1), fminf(t2,t3)));
        }
        g_sitechan[(size_t)(blockIdx.x*2 + sl2)*64 + cch] = ps;
#pragma unroll
        for (int off = 16; off; off >>= 1)
            pm = fminf(pm, __shfl_xor_sync(0xffffffffu, pm, off));
        if ((tid & 31) == 0) pminw[tid >> 5] = pm;
    }

    int sl = tid >> 6;
    int s  = tid & 63;
    int ti = s >> 3, tj = s & 7;
    const float* As = Ab + sl*3328;
    const float* Gs = Gb + sl*3328;

    float acc[8][8];
#pragma unroll
    for (int ii = 0; ii < 8; ii++)
#pragma unroll
        for (int jj = 0; jj < 8; jj++) acc[ii][jj] = 0.f;

    for (int l4 = 0; l4 < 12; l4++) {
#pragma unroll
        for (int half = 0; half < 2; half++) {
            float4 av[4];
#pragma unroll
            for (int k = 0; k < 4; k++)
                av[k] = *(const float4*)&As[(ti + 8*(half*4+k))*52 + l4*4];
#pragma unroll
            for (int jj = 0; jj < 8; jj++) {
                float4 gv = *(const float4*)&Gs[(tj + 8*jj)*52 + l4*4];
#pragma unroll
                for (int k = 0; k < 4; k++) {
                    int ii = half*4 + k;
                    acc[ii][jj] = fmaf(av[k].x, gv.x, acc[ii][jj]);
                    acc[ii][jj] = fmaf(av[k].y, gv.y, acc[ii][jj]);
                    acc[ii][jj] = fmaf(av[k].z, gv.z, acc[ii][jj]);
                    acc[ii][jj] = fmaf(av[k].w, gv.w, acc[ii][jj]);
                }
            }
        }
    }

    float lmin = acc[0][0], lsum = 0.f;
#pragma unroll
    for (int ii = 0; ii < 8; ii++)
#pragma unroll
        for (int jj = 0; jj < 8; jj++) {
            lmin = fminf(lmin, acc[ii][jj]);
            lsum += acc[ii][jj];
        }
#pragma unroll
    for (int off = 16; off; off >>= 1) {
        lmin = fminf(lmin, __shfl_xor_sync(0xffffffffu, lmin, off));
        lsum += __shfl_xor_sync(0xffffffffu, lsum, off);
    }
    int wid = tid >> 5, lane = tid & 31;
    if (!lane) { rmin[wid] = lmin; rsum[wid] = lsum; }
    __syncthreads();
    if (tid == 0) {
        float m = fminf(fminf(rmin[0], rmin[1]), fminf(rmin[2], rmin[3]));
        atomicMin(&g_min_d_key, fkey(m));
        float pm = fminf(fminf(pminw[0], pminw[1]), fminf(pminw[2], pminw[3]));
        atomicMin(&g_min_p_key, fkey(pm));
    }
    if (s == 0) {
        int w0 = sl*2;
        g_sitesum[blockIdx.x*2 + sl] = rsum[w0] + rsum[w0+1];
    }
}

// ---------------- reduce per-(b,c) p sums -> inverted denominator -----------
__global__ void k_reduce_p2() {     // BB*CC blocks x 256 threads
    int bc = blockIdx.x;
    int b = bc >> 6, c = bc & 63;
    int tid = threadIdx.x;
    float s = 0.f;
    for (int i = tid; i < HWn; i += 256)
        s += g_sitechan[(size_t)(b*HWn + i)*64 + c];
    __shared__ float sh[256];
    sh[tid] = s;
    __syncthreads();
    for (int st = 128; st > 0; st >>= 1) {
        if (tid < st) sh[tid] += sh[tid + st];
        __syncthreads();
    }
    if (tid == 0) {
        float m1 = funkey(g_min_p_key);
        g_inv1[bc] = 1.0f / (sh[0] - m1 * (float)SS);
    }
}

__global__ void k_reduce_d() {    // BB blocks x 256 threads
    int b = blockIdx.x, tid = threadIdx.x;
    float s = 0.f;
    for (int i = tid; i < HWn; i += 256) s += g_sitesum[b * HWn + i];
    __shared__ float sh[256];
    sh[tid] = s;
    __syncthreads();
    for (int st = 128; st > 0; st >>= 1) {
        if (tid < st) sh[tid] += sh[tid + st];
        __syncthreads();
    }
    if (tid == 0) {
        float m2 = funkey(g_min_d_key);
        g_inv2[b] = 1.0f / (sh[0] - m2 * 9437184.0f);  // HW*C*C per batch
    }
}

// -------- d (+ fused p): D = (G*(A^T X) - m2*colsum(X))*inv2; p in load loop
#define KD_SMEM ((3328+3328+3264+2496+48)*4)
__global__ __launch_bounds__(128, 4) void k_d(const float* __restrict__ x,
                                              float* __restrict__ outp,
                                              float* __restrict__ outd) {
    extern __shared__ float dyn[];
    float* As = dyn;            // 64*52
    float* Xs = As + 3328;      // 64*52
    float* Gt = Xs + 3328;      // 48*68
    float* Ms = Gt + 3264;      // 48*52
    float* cs = Ms + 2496;      // 48
    int tid = threadIdx.x;
    int site = blockIdx.x;
    int b = site / HWn, hw = site - b*HWn;
    size_t gb = (size_t)b*CC*SS + (size_t)hw*LL;

    float m1 = funkey(g_min_p_key);
    for (int i = tid; i < 64*12; i += 128) {
        int c = i / 12, lv = i - c*12;
        size_t off = gb + (size_t)c*SS + lv*4;
        float4 a  = *(const float4*)(g_tx + off);
        float4 xv = *(const float4*)(x + off);
        float4 gg = *(const float4*)(g_tg + off);
        *(float4*)&As[c*52 + lv*4] = a;
        *(float4*)&Xs[c*52 + lv*4] = xv;
        Gt[(lv*4+0)*68 + c] = gg.x;
        Gt[(lv*4+1)*68 + c] = gg.y;
        Gt[(lv*4+2)*68 + c] = gg.z;
        Gt[(lv*4+3)*68 + c] = gg.w;
        // fused p output
        float inv1 = g_inv1[b*64 + c];
        float4 o;
        o.x = (a.x*gg.x - m1) * xv.x * inv1;
        o.y = (a.y*gg.y - m1) * xv.y * inv1;
        o.z = (a.z*gg.z - m1) * xv.z * inv1;
        o.w = (a.w*gg.w - m1) * xv.w * inv1;
        *(float4*)(outp + off) = o;
    }
    __syncthreads();

    if (tid < 48) {
        float s = 0.f;
#pragma unroll 8
        for (int c = 0; c < 64; c++) s += Xs[c*52 + tid];
        cs[tid] = s;
    }

    // phase 1: M[lp][l] = sum_c A[c][lp] * X[c][l]
    {
        int ti = tid >> 3;
        int tj = tid & 7;
        float acc[3][6];
#pragma unroll
        for (int ii = 0; ii < 3; ii++)
#pragma unroll
            for (int jj = 0; jj < 6; jj++) acc[ii][jj] = 0.f;

#pragma unroll 4
        for (int c = 0; c < 64; c++) {
            float a0 = As[c*52 + ti*3 + 0];
            float a1 = As[c*52 + ti*3 + 1];
            float a2 = As[c*52 + ti*3 + 2];
            float xv[6];
#pragma unroll
            for (int jj = 0; jj < 6; jj++) xv[jj] = Xs[c*52 + tj*6 + jj];
#pragma unroll
            for (int jj = 0; jj < 6; jj++) {
                acc[0][jj] = fmaf(a0, xv[jj], acc[0][jj]);
                acc[1][jj] = fmaf(a1, xv[jj], acc[1][jj]);
                acc[2][jj] = fmaf(a2, xv[jj], acc[2][jj]);
            }
        }
#pragma unroll
        for (int ii = 0; ii < 3; ii++)
#pragma unroll
            for (int jj = 0; jj < 6; jj++)
                Ms[(ti*3+ii)*52 + tj*6 + jj] = acc[ii][jj];
    }
    __syncthreads();

    // phase 2: D[j][l] = sum_lp Gt[lp][j] * M[lp][l]
    float m2  = funkey(g_min_d_key);
    float inv = g_inv2[b];
    {
        int ti = tid >> 4;
        int tj = tid & 15;
        float acc[8][3];
#pragma unroll
        for (int k = 0; k < 8; k++)
#pragma unroll
            for (int m = 0; m < 3; m++) acc[k][m] = 0.f;

#pragma unroll 4
        for (int lp = 0; lp < 48; lp++) {
            float4 gA = *(const float4*)&Gt[lp*68 + ti*8];
            float4 gB = *(const float4*)&Gt[lp*68 + ti*8 + 4];
            float gk[8] = {gA.x,gA.y,gA.z,gA.w,gB.x,gB.y,gB.z,gB.w};
            float q0 = Ms[lp*52 + tj*3 + 0];
            float q1 = Ms[lp*52 + tj*3 + 1];
            float q2 = Ms[lp*52 + tj*3 + 2];
#pragma unroll
            for (int k = 0; k < 8; k++) {
                acc[k][0] = fmaf(gk[k], q0, acc[k][0]);
                acc[k][1] = fmaf(gk[k], q1, acc[k][1]);
                acc[k][2] = fmaf(gk[k], q2, acc[k][2]);
            }
        }

        float cc0 = cs[tj*3+0], cc1 = cs[tj*3+1], cc2 = cs[tj*3+2];
#pragma unroll
        for (int k = 0; k < 8; k++) {
            int j = ti*8 + k;
            size_t ob = gb + (size_t)j*SS + tj*3;
            outd[ob+0] = (acc[k][0] - m2*cc0) * inv;
            outd[ob+1] = (acc[k][1] - m2*cc1) * inv;
            outd[ob+2] = (acc[k][2] - m2*cc2) * inv;
        }
    }
}

// ---------------- launch ----------------------------------------------------
extern "C" void kernel_launch(void* const* d_in, const int* in_sizes, int n_in,
                              void* d_out, int out_size) {
    const float* x  = (const float*)d_in[0];
    const float* g  = (const float*)d_in[1];
    const float* W1 = (const float*)d_in[2];
    const float* b1 = (const float*)d_in[3];
    const float* W2 = (const float*)d_in[4];
    const float* b2 = (const float*)d_in[5];

    float* out  = (float*)d_out;
    float* outp = out;
    float* outd = out + (size_t)TOTAL;

    cudaFuncSetAttribute(k_chanmix, cudaFuncAttributeMaxDynamicSharedMemorySize, CM_SMEM);
    cudaFuncSetAttribute(k_stats_d, cudaFuncAttributeMaxDynamicSharedMemorySize, SD_SMEM);
    cudaFuncSetAttribute(k_d,       cudaFuncAttributeMaxDynamicSharedMemorySize, KD_SMEM);

    k_init<<<1, 1>>>();

    { dim3 gx(SS/128,  BB); k_chanmix<<<gx, 128, CM_SMEM>>>(x, W1, b1, 0, SS); }
    { dim3 gg(GSS/128, BB); k_chanmix<<<gg, 128, CM_SMEM>>>(g, W2, b2, 1, GSS); }
    { dim3 gu(HH, BB*CC);   k_upsample<<<gu, dim3(24, 16)>>>(); }

    k_stats_d<<<NSITES/2, 128, SD_SMEM>>>();
    k_reduce_p2<<<BB*CC, 256>>>();
    k_reduce_d<<<BB, 256>>>();

    k_d<<<NSITES, 128, KD_SMEM>>>(x, outp, outd);
}